// round 4
// baseline (speedup 1.0000x reference)
#include <cuda_runtime.h>
#include <math.h>

// LSTM: T=512, B=64, I=H=512.  out[t,b,h] = h_t.
// Kernel 1: x_proj[t][g*512+h][b] = x @ W_ih^T + (b_ih + b_hh)
// Kernel 2: persistent 128-CTA recurrence, 4 independent batch-quarter groups,
//           distributed per-CTA release/acquire flags (no central barrier).

#define Tq 512
#define Bq 64
#define Hq 512
#define G4 2048
#define WSTR 516                 // padded row stride (floats), float4-aligned
#define WSTR4 129

typedef unsigned long long ull;

__device__ float g_xp[(size_t)Tq * G4 * Bq];   // 256MB scratch
__device__ unsigned g_flags[4][32];            // per-CTA monotonic step flags

__device__ __forceinline__ ull pk2(float lo, float hi) {
    ull r; asm("mov.b64 %0, {%1, %2};" : "=l"(r) : "f"(lo), "f"(hi)); return r;
}
__device__ __forceinline__ float2 upk2(ull v) {
    float2 r; asm("mov.b64 {%0, %1}, %2;" : "=f"(r.x), "=f"(r.y) : "l"(v)); return r;
}
__device__ __forceinline__ ull ffma2(ull a, ull b, ull c) {
    ull d; asm("fma.rn.f32x2 %0, %1, %2, %3;" : "=l"(d) : "l"(a), "l"(b), "l"(c)); return d;
}
__device__ __forceinline__ void cpa16(float* s, const float* g) {
    unsigned sa = (unsigned)__cvta_generic_to_shared(s);
    asm volatile("cp.async.cg.shared.global [%0], [%1], 16;" :: "r"(sa), "l"(g));
}
__device__ __forceinline__ void cpcommit() { asm volatile("cp.async.commit_group;"); }
template <int N> __device__ __forceinline__ void cpwait() {
    asm volatile("cp.async.wait_group %0;" :: "n"(N));
}
__device__ __forceinline__ float sigf(float x) {
    return __fdividef(1.f, 1.f + __expf(-x));
}
__device__ __forceinline__ float tanhx(float x) {
    return __fdividef(2.f, 1.f + __expf(-2.f * x)) - 1.f;
}

// ---------------------------------------------------------------------------
// Kernel 1: C[M=32768, N=2048] = x[M,512] * W_ih[N,512]^T + bias
// ---------------------------------------------------------------------------
__global__ __launch_bounds__(256, 2) void gemm_xproj(
    const float* __restrict__ A, const float* __restrict__ W,
    const float* __restrict__ bih, const float* __restrict__ bhh)
{
    __shared__ float As[16][128];
    __shared__ float Bs[16][128];
    const int tid = threadIdx.x;
    const int m0 = blockIdx.y * 128;
    const int n0 = blockIdx.x * 128;
    const int lrow = tid >> 1;
    const int lc = (tid & 1) * 8;
    const int tmq = tid & 15;
    const int tn = (tid >> 4) * 8;

    const float* Ap = A + (size_t)(m0 + lrow) * 512 + lc;
    const float* Bp = W + (size_t)(n0 + lrow) * 512 + lc;

    ull acc[8][4];
#pragma unroll
    for (int j = 0; j < 8; j++)
#pragma unroll
        for (int p = 0; p < 4; p++) acc[j][p] = 0ull;

    float4 a0 = *(const float4*)(Ap);
    float4 a1 = *(const float4*)(Ap + 4);
    float4 b0 = *(const float4*)(Bp);
    float4 b1 = *(const float4*)(Bp + 4);

    const float4* As4 = (const float4*)As;
    const float4* Bs4 = (const float4*)Bs;

#pragma unroll 1
    for (int k0 = 0; k0 < 512; k0 += 16) {
        __syncthreads();
        As[lc + 0][lrow] = a0.x; As[lc + 1][lrow] = a0.y;
        As[lc + 2][lrow] = a0.z; As[lc + 3][lrow] = a0.w;
        As[lc + 4][lrow] = a1.x; As[lc + 5][lrow] = a1.y;
        As[lc + 6][lrow] = a1.z; As[lc + 7][lrow] = a1.w;
        Bs[lc + 0][lrow] = b0.x; Bs[lc + 1][lrow] = b0.y;
        Bs[lc + 2][lrow] = b0.z; Bs[lc + 3][lrow] = b0.w;
        Bs[lc + 4][lrow] = b1.x; Bs[lc + 5][lrow] = b1.y;
        Bs[lc + 6][lrow] = b1.z; Bs[lc + 7][lrow] = b1.w;
        __syncthreads();
        if (k0 + 16 < 512) {
            a0 = *(const float4*)(Ap + k0 + 16);
            a1 = *(const float4*)(Ap + k0 + 20);
            b0 = *(const float4*)(Bp + k0 + 16);
            b1 = *(const float4*)(Bp + k0 + 20);
        }
#pragma unroll 8
        for (int kk = 0; kk < 16; kk++) {
            float4 av0 = As4[kk * 32 + tmq];
            float4 av1 = As4[kk * 32 + 16 + tmq];
            ull am[4] = { pk2(av0.x, av0.y), pk2(av0.z, av0.w),
                          pk2(av1.x, av1.y), pk2(av1.z, av1.w) };
            float4 bv0 = Bs4[kk * 32 + (tid >> 4) * 2];
            float4 bv1 = Bs4[kk * 32 + (tid >> 4) * 2 + 1];
            float bb[8] = { bv0.x, bv0.y, bv0.z, bv0.w, bv1.x, bv1.y, bv1.z, bv1.w };
#pragma unroll
            for (int j = 0; j < 8; j++) {
                ull bd = pk2(bb[j], bb[j]);
#pragma unroll
                for (int p = 0; p < 4; p++) acc[j][p] = ffma2(bd, am[p], acc[j][p]);
            }
        }
    }

#pragma unroll
    for (int j = 0; j < 8; j++) {
        int n = n0 + tn + j;
        float bv = bih[n] + bhh[n];
#pragma unroll
        for (int p = 0; p < 4; p++) {
            float2 v = upk2(acc[j][p]);
            v.x += bv; v.y += bv;
            int m = m0 + tmq * 4 + (p & 1) * 2 + (p >> 1) * 64;
            int tt = m >> 6, bb2 = m & 63;
            *(float2*)&g_xp[((size_t)tt * G4 + n) * Bq + bb2] = v;
        }
    }
}

// ---------------------------------------------------------------------------
// Kernel 2: persistent recurrence, grid 128 = (bq 0..3) x (hg 0..31).
// CTA covers b in [bq*16,+16), hc in [hg*16,+16). 256 threads: one (b,hc) each.
// Cross-CTA sync: CTA (bq,hg) at step t polls the 32 flags of group bq
// (warp-0 lanes, one coalesced acquire load per iteration). Producer sets its
// flag with st.release after storing its h tile. Groups are independent.
// ---------------------------------------------------------------------------
__global__ __launch_bounds__(256, 1) void lstm_rec(
    const float* __restrict__ Whh, float* __restrict__ out)
{
    extern __shared__ float sm[];
    float* Ws = sm;                         // [64 rows = hcl*4+g][WSTR]
    float* hs = sm + 64 * WSTR;             // [16 b][WSTR]
    float* ho = hs + 16 * WSTR;             // [16 b][16 hc] store staging
    const int tid = threadIdx.x;
    const int bl = tid & 15;                // local batch
    const int hcl = tid >> 4;               // local h-column
    const int bq = blockIdx.x >> 5;         // group 0..3
    const int hg = blockIdx.x & 31;         // 0..31
    const int b0 = bq * 16;
    const int hc0 = hg * 16;
    const int hcE = hc0 + hcl;
    const int bE = b0 + bl;

    // monotonic epoch base (uniform across CTAs at kernel entry; replay-safe)
    const unsigned base = *((volatile unsigned*)&g_flags[bq][hg]);

    // load W_hh slice once: row r = hcl*4+g  <-  Whh[g*512 + hc0 + hcl][k]
    for (int i = tid; i < 64 * 128; i += 256) {
        int r = i >> 7;                     // 0..63
        int c4 = i & 127;
        int grow = (r & 3) * 512 + hc0 + (r >> 2);
        ((float4*)(Ws + r * WSTR))[c4] = ((const float4*)(Whh + (size_t)grow * 512))[c4];
    }
    __syncthreads();

    const float4* hp4 = (const float4*)hs + bl * WSTR4;
    const float4* w0p = (const float4*)Ws + (hcl * 4 + 0) * WSTR4;
    const float4* w1p = (const float4*)Ws + (hcl * 4 + 1) * WSTR4;
    const float4* w2p = (const float4*)Ws + (hcl * 4 + 2) * WSTR4;
    const float4* w3p = (const float4*)Ws + (hcl * 4 + 3) * WSTR4;
    float cst = 0.f;

#pragma unroll 1
    for (int t = 0; t < Tq; t++) {
        // x_proj for this (b,hc), issued early (consumed ~4000 cyc later)
        const float* xpt = g_xp + (size_t)t * (G4 * Bq) + (size_t)hcE * Bq + bE;
        float g0 = __ldg(xpt + 0 * 512 * Bq);
        float g1 = __ldg(xpt + 1 * 512 * Bq);
        float g2 = __ldg(xpt + 2 * 512 * Bq);
        float g3 = __ldg(xpt + 3 * 512 * Bq);

        if (t > 0) {
            // ---- wait for the 32 producers of this group (h[t-1] ready) ----
            if (tid < 32) {
                const unsigned* fp = &g_flags[bq][tid];
                unsigned tgt = base + (unsigned)t;
                unsigned v;
                do {
                    asm volatile("ld.acquire.gpu.u32 %0, [%1];"
                                 : "=r"(v) : "l"(fp) : "memory");
                } while (__any_sync(0xffffffffu, v < tgt));
            }
            __syncthreads();

            const float* hp = out + (size_t)(t - 1) * (Bq * Hq) + (size_t)b0 * Hq;
            // issue chunk 0 (K 0..127): 512 float4, 2 per thread
#pragma unroll
            for (int r = 0; r < 2; r++) {
                int j = tid + r * 256;
                int row = j >> 5, kf = j & 31;
                cpa16(hs + row * WSTR + kf * 4, hp + row * 512 + kf * 4);
            }
            cpcommit();

            ull a0 = 0, a1 = 0, a2 = 0, a3 = 0;
#pragma unroll 1
            for (int c = 0; c < 4; c++) {
                if (c < 3) {                 // issue chunk c+1, wait chunk c
                    int kb = (c + 1) * 128;
#pragma unroll
                    for (int r = 0; r < 2; r++) {
                        int j = tid + r * 256;
                        int row = j >> 5, kf = j & 31;
                        cpa16(hs + row * WSTR + kb + kf * 4, hp + row * 512 + kb + kf * 4);
                    }
                    cpcommit();
                    cpwait<1>();
                } else {
                    cpwait<0>();
                }
                __syncthreads();             // publish chunk c (regions disjoint)
                int kb4 = c * 32;
#pragma unroll 8
                for (int k4 = 0; k4 < 32; k4++) {
                    float4 h4 = hp4[kb4 + k4];
                    ull h01 = pk2(h4.x, h4.y), h23 = pk2(h4.z, h4.w);
                    float4 w0 = w0p[kb4 + k4];
                    float4 w1 = w1p[kb4 + k4];
                    float4 w2 = w2p[kb4 + k4];
                    float4 w3 = w3p[kb4 + k4];
                    a0 = ffma2(h01, pk2(w0.x, w0.y), a0);
                    a1 = ffma2(h01, pk2(w1.x, w1.y), a1);
                    a2 = ffma2(h01, pk2(w2.x, w2.y), a2);
                    a3 = ffma2(h01, pk2(w3.x, w3.y), a3);
                    a0 = ffma2(h23, pk2(w0.z, w0.w), a0);
                    a1 = ffma2(h23, pk2(w1.z, w1.w), a1);
                    a2 = ffma2(h23, pk2(w2.z, w2.w), a2);
                    a3 = ffma2(h23, pk2(w3.z, w3.w), a3);
                }
            }
            float2 v0 = upk2(a0), v1 = upk2(a1), v2 = upk2(a2), v3 = upk2(a3);
            g0 += v0.x + v0.y;
            g1 += v1.x + v1.y;
            g2 += v2.x + v2.y;
            g3 += v3.x + v3.y;
        }

        float iv = sigf(g0);
        float fv = sigf(g1);
        float gv = tanhx(g2);
        float ov = sigf(g3);
        cst = fv * cst + iv * gv;
        float hv = ov * tanhx(cst);

        // stage h tile through smem; 64 threads store coalesced float4,
        // then signal via named barrier + release flag. Warps 2..7 run ahead.
        ho[bl * 16 + hcl] = hv;
        __syncthreads();
        if (tid < 64) {
            int row = tid >> 2, f4 = tid & 3;
            float4 v = ((const float4*)(ho + row * 16))[f4];
            *(float4*)&out[(size_t)t * (Bq * Hq) + (size_t)(b0 + row) * Hq + hc0 + f4 * 4] = v;
            asm volatile("bar.sync 1, 64;" ::: "memory");
            if (tid == 0 && t < Tq - 1) {
                unsigned nv = base + (unsigned)(t + 1);
                asm volatile("st.release.gpu.u32 [%0], %1;"
                             :: "l"(&g_flags[bq][hg]), "r"(nv) : "memory");
            }
        }
    }
}

#define REC_SMEM ((64 * WSTR + 16 * WSTR + 16 * 16) * 4)

extern "C" void kernel_launch(void* const* d_in, const int* in_sizes, int n_in,
                              void* d_out, int out_size) {
    const float* x   = (const float*)d_in[0];   // [512,64,512]
    const float* Wih = (const float*)d_in[1];   // [2048,512]
    const float* Whh = (const float*)d_in[2];   // [2048,512]
    const float* bih = (const float*)d_in[3];   // [2048]
    const float* bhh = (const float*)d_in[4];   // [2048]
    float* out = (float*)d_out;                 // [512,64,512]

    cudaFuncSetAttribute(lstm_rec, cudaFuncAttributeMaxDynamicSharedMemorySize, REC_SMEM);

    dim3 g1(G4 / 128, (Tq * Bq) / 128);         // (16, 256)
    gemm_xproj<<<g1, 256>>>(x, Wih, bih, bhh);
    lstm_rec<<<128, 256, REC_SMEM>>>(Whh, out);
}

// round 5
// speedup vs baseline: 1.7909x; 1.7909x over previous
#include <cuda_runtime.h>
#include <math.h>

// LSTM: T=512, B=64, I=H=512.  out[t,b,h] = h_t.
// Kernel 1: x_proj[t][g*512+h][b] = x @ W_ih^T + (b_ih + b_hh)
// Kernel 2: persistent recurrence, 128 CTAs x 512 threads,
//           4 independent batch-quarter groups, central per-group counter.

#define Tq 512
#define Bq 64
#define Hq 512
#define G4 2048
#define WSTR 516                 // row stride (floats): 2064B % 128 == 16 -> bank-spread
#define PEXR 72                  // pex row stride (floats)

typedef unsigned long long ull;

__device__ float g_xp[(size_t)Tq * G4 * Bq];   // 256MB scratch
__device__ unsigned g_cnt[4 * 32];             // per-group counters, 128B apart

__device__ __forceinline__ ull pk2(float lo, float hi) {
    ull r; asm("mov.b64 %0, {%1, %2};" : "=l"(r) : "f"(lo), "f"(hi)); return r;
}
__device__ __forceinline__ float2 upk2(ull v) {
    float2 r; asm("mov.b64 {%0, %1}, %2;" : "=f"(r.x), "=f"(r.y) : "l"(v)); return r;
}
__device__ __forceinline__ ull ffma2(ull a, ull b, ull c) {
    ull d; asm("fma.rn.f32x2 %0, %1, %2, %3;" : "=l"(d) : "l"(a), "l"(b), "l"(c)); return d;
}
__device__ __forceinline__ void cpa16(float* s, const float* g) {
    unsigned sa = (unsigned)__cvta_generic_to_shared(s);
    asm volatile("cp.async.cg.shared.global [%0], [%1], 16;" :: "r"(sa), "l"(g));
}
__device__ __forceinline__ void cpcommit() { asm volatile("cp.async.commit_group;"); }
template <int N> __device__ __forceinline__ void cpwait() {
    asm volatile("cp.async.wait_group %0;" :: "n"(N));
}
__device__ __forceinline__ float sigf(float x) {
    return __fdividef(1.f, 1.f + __expf(-x));
}
__device__ __forceinline__ float tanhx(float x) {
    return __fdividef(2.f, 1.f + __expf(-2.f * x)) - 1.f;
}

// ---------------------------------------------------------------------------
// Kernel 1: C[M=32768, N=2048] = x[M,512] * W_ih[N,512]^T + bias
// ---------------------------------------------------------------------------
__global__ __launch_bounds__(256, 2) void gemm_xproj(
    const float* __restrict__ A, const float* __restrict__ W,
    const float* __restrict__ bih, const float* __restrict__ bhh)
{
    __shared__ float As[16][128];
    __shared__ float Bs[16][128];
    const int tid = threadIdx.x;
    const int m0 = blockIdx.y * 128;
    const int n0 = blockIdx.x * 128;
    const int lrow = tid >> 1;
    const int lc = (tid & 1) * 8;
    const int tmq = tid & 15;
    const int tn = (tid >> 4) * 8;

    const float* Ap = A + (size_t)(m0 + lrow) * 512 + lc;
    const float* Bp = W + (size_t)(n0 + lrow) * 512 + lc;

    ull acc[8][4];
#pragma unroll
    for (int j = 0; j < 8; j++)
#pragma unroll
        for (int p = 0; p < 4; p++) acc[j][p] = 0ull;

    float4 a0 = *(const float4*)(Ap);
    float4 a1 = *(const float4*)(Ap + 4);
    float4 b0 = *(const float4*)(Bp);
    float4 b1 = *(const float4*)(Bp + 4);

    const float4* As4 = (const float4*)As;
    const float4* Bs4 = (const float4*)Bs;

#pragma unroll 1
    for (int k0 = 0; k0 < 512; k0 += 16) {
        __syncthreads();
        As[lc + 0][lrow] = a0.x; As[lc + 1][lrow] = a0.y;
        As[lc + 2][lrow] = a0.z; As[lc + 3][lrow] = a0.w;
        As[lc + 4][lrow] = a1.x; As[lc + 5][lrow] = a1.y;
        As[lc + 6][lrow] = a1.z; As[lc + 7][lrow] = a1.w;
        Bs[lc + 0][lrow] = b0.x; Bs[lc + 1][lrow] = b0.y;
        Bs[lc + 2][lrow] = b0.z; Bs[lc + 3][lrow] = b0.w;
        Bs[lc + 4][lrow] = b1.x; Bs[lc + 5][lrow] = b1.y;
        Bs[lc + 6][lrow] = b1.z; Bs[lc + 7][lrow] = b1.w;
        __syncthreads();
        if (k0 + 16 < 512) {
            a0 = *(const float4*)(Ap + k0 + 16);
            a1 = *(const float4*)(Ap + k0 + 20);
            b0 = *(const float4*)(Bp + k0 + 16);
            b1 = *(const float4*)(Bp + k0 + 20);
        }
#pragma unroll 8
        for (int kk = 0; kk < 16; kk++) {
            float4 av0 = As4[kk * 32 + tmq];
            float4 av1 = As4[kk * 32 + 16 + tmq];
            ull am[4] = { pk2(av0.x, av0.y), pk2(av0.z, av0.w),
                          pk2(av1.x, av1.y), pk2(av1.z, av1.w) };
            float4 bv0 = Bs4[kk * 32 + (tid >> 4) * 2];
            float4 bv1 = Bs4[kk * 32 + (tid >> 4) * 2 + 1];
            float bb[8] = { bv0.x, bv0.y, bv0.z, bv0.w, bv1.x, bv1.y, bv1.z, bv1.w };
#pragma unroll
            for (int j = 0; j < 8; j++) {
                ull bd = pk2(bb[j], bb[j]);
#pragma unroll
                for (int p = 0; p < 4; p++) acc[j][p] = ffma2(bd, am[p], acc[j][p]);
            }
        }
    }

#pragma unroll
    for (int j = 0; j < 8; j++) {
        int n = n0 + tn + j;
        float bv = bih[n] + bhh[n];
#pragma unroll
        for (int p = 0; p < 4; p++) {
            float2 v = upk2(acc[j][p]);
            v.x += bv; v.y += bv;
            int m = m0 + tmq * 4 + (p & 1) * 2 + (p >> 1) * 64;
            int tt = m >> 6, bb2 = m & 63;
            *(float2*)&g_xp[((size_t)tt * G4 + n) * Bq + bb2] = v;
        }
    }
}

// ---------------------------------------------------------------------------
// Kernel 2: persistent recurrence, grid 128 = (bq 0..3) x (hg 0..31),
// 512 threads: tid = bq4 + 4*hcl + 64*ks  (bq4: 4 batches {bq4,+4,+8,+12},
// hcl: local h-col 0..15, ks: K-slice 0..7 of 64 floats).
// Thread holds acc[4 b][4 g] -> 8 LDS per 32 FFMA2 (crossbar << FMA floor).
// Per-ks group (64 thr) stages its own 4KB h K-slice via cp.async + named bar.
// Elementwise by tid<256 = (eb 0..15, ehcl 0..15) after K-split-8 reduction.
// ---------------------------------------------------------------------------
__global__ __launch_bounds__(512, 1) void lstm_rec(
    const float* __restrict__ Whh, float* __restrict__ out)
{
    extern __shared__ float sm[];
    float* Ws = sm;                          // [64 rows = g*16+hcl][WSTR]
    float* hs = sm + 64 * WSTR;              // [16 b][WSTR]
    float* pex = hs + 16 * WSTR;             // [(ks*16+b)][PEXR] : hcl*4+g
    float* ho = pex + 128 * PEXR;            // [16 b][16 hc]
    const int tid = threadIdx.x;
    const int bq4 = tid & 3;
    const int hcl = (tid >> 2) & 15;
    const int ks = tid >> 6;
    const int ks64 = ks * 64;
    const int bq = blockIdx.x >> 5;          // group 0..3
    const int hg = blockIdx.x & 31;
    const int b0 = bq * 16;
    const int hc0 = hg * 16;
    const int eb = tid & 15;                 // elementwise role (tid<256)
    const int ehcl = (tid >> 4) & 15;
    unsigned* cnt = &g_cnt[bq * 32];

    // load W_hh slice once: row r = g*16+hr  <-  Whh[g*512 + hc0 + hr][k]
    for (int i = tid; i < 64 * 128; i += 512) {
        int r = i >> 7;
        int c4 = i & 127;
        int grow = (r >> 4) * 512 + hc0 + (r & 15);
        ((float4*)(Ws + r * WSTR))[c4] = ((const float4*)(Whh + (size_t)grow * 512))[c4];
    }
    __syncthreads();

    const float4* wp0 = (const float4*)(Ws + (0 * 16 + hcl) * WSTR + ks64);
    const float4* wp1 = (const float4*)(Ws + (1 * 16 + hcl) * WSTR + ks64);
    const float4* wp2 = (const float4*)(Ws + (2 * 16 + hcl) * WSTR + ks64);
    const float4* wp3 = (const float4*)(Ws + (3 * 16 + hcl) * WSTR + ks64);
    const float4* hq0 = (const float4*)(hs + (bq4 + 0) * WSTR + ks64);
    const float4* hq1 = (const float4*)(hs + (bq4 + 4) * WSTR + ks64);
    const float4* hq2 = (const float4*)(hs + (bq4 + 8) * WSTR + ks64);
    const float4* hq3 = (const float4*)(hs + (bq4 + 12) * WSTR + ks64);
    float cst = 0.f;

#pragma unroll 1
    for (int t = 0; t < Tq; t++) {
        // x_proj (elementwise threads only), issued early
        float xv0, xv1, xv2, xv3;
        if (tid < 256) {
            const float* xpt = g_xp + (size_t)t * (G4 * Bq)
                             + (size_t)(hc0 + ehcl) * Bq + b0 + eb;
            xv0 = __ldg(xpt + 0 * 512 * Bq);
            xv1 = __ldg(xpt + 1 * 512 * Bq);
            xv2 = __ldg(xpt + 2 * 512 * Bq);
            xv3 = __ldg(xpt + 3 * 512 * Bq);
        }

        if (t > 0) {
            // ---- group barrier: h[t-1] of all 32 CTAs in this group ready ----
            if (tid == 0) {
                unsigned tgt = 32u * (unsigned)t;
                unsigned v;
                do {
                    asm volatile("ld.acquire.gpu.u32 %0, [%1];"
                                 : "=r"(v) : "l"(cnt) : "memory");
                } while (v < tgt);
            }
            __syncthreads();

            // ---- stage own K-slice (4KB) : 64 threads, 4 cp.async each ----
            const float* hp = out + (size_t)(t - 1) * (Bq * Hq) + (size_t)b0 * Hq;
            int l = tid & 63;
#pragma unroll
            for (int r = 0; r < 4; r++) {
                int j = l + r * 64;
                int row = j >> 4, kf = j & 15;
                cpa16(hs + row * WSTR + ks64 + kf * 4, hp + row * 512 + ks64 + kf * 4);
            }
            cpcommit();
            cpwait<0>();
            asm volatile("bar.sync %0, 64;" :: "r"(1 + ks) : "memory");

            // ---- compute: acc[4 b][4 g] over 64-float K-slice ----
            ull acc[4][4];
#pragma unroll
            for (int j = 0; j < 4; j++)
#pragma unroll
                for (int g = 0; g < 4; g++) acc[j][g] = 0ull;

#pragma unroll 8
            for (int k4 = 0; k4 < 16; k4++) {
                float4 w0 = wp0[k4], w1 = wp1[k4], w2 = wp2[k4], w3 = wp3[k4];
                ull w0a = pk2(w0.x, w0.y), w0b = pk2(w0.z, w0.w);
                ull w1a = pk2(w1.x, w1.y), w1b = pk2(w1.z, w1.w);
                ull w2a = pk2(w2.x, w2.y), w2b = pk2(w2.z, w2.w);
                ull w3a = pk2(w3.x, w3.y), w3b = pk2(w3.z, w3.w);
                float4 h0 = hq0[k4], h1 = hq1[k4], h2 = hq2[k4], h3 = hq3[k4];
                ull hA, hB;
                hA = pk2(h0.x, h0.y); hB = pk2(h0.z, h0.w);
                acc[0][0] = ffma2(hA, w0a, acc[0][0]); acc[0][0] = ffma2(hB, w0b, acc[0][0]);
                acc[0][1] = ffma2(hA, w1a, acc[0][1]); acc[0][1] = ffma2(hB, w1b, acc[0][1]);
                acc[0][2] = ffma2(hA, w2a, acc[0][2]); acc[0][2] = ffma2(hB, w2b, acc[0][2]);
                acc[0][3] = ffma2(hA, w3a, acc[0][3]); acc[0][3] = ffma2(hB, w3b, acc[0][3]);
                hA = pk2(h1.x, h1.y); hB = pk2(h1.z, h1.w);
                acc[1][0] = ffma2(hA, w0a, acc[1][0]); acc[1][0] = ffma2(hB, w0b, acc[1][0]);
                acc[1][1] = ffma2(hA, w1a, acc[1][1]); acc[1][1] = ffma2(hB, w1b, acc[1][1]);
                acc[1][2] = ffma2(hA, w2a, acc[1][2]); acc[1][2] = ffma2(hB, w2b, acc[1][2]);
                acc[1][3] = ffma2(hA, w3a, acc[1][3]); acc[1][3] = ffma2(hB, w3b, acc[1][3]);
                hA = pk2(h2.x, h2.y); hB = pk2(h2.z, h2.w);
                acc[2][0] = ffma2(hA, w0a, acc[2][0]); acc[2][0] = ffma2(hB, w0b, acc[2][0]);
                acc[2][1] = ffma2(hA, w1a, acc[2][1]); acc[2][1] = ffma2(hB, w1b, acc[2][1]);
                acc[2][2] = ffma2(hA, w2a, acc[2][2]); acc[2][2] = ffma2(hB, w2b, acc[2][2]);
                acc[2][3] = ffma2(hA, w3a, acc[2][3]); acc[2][3] = ffma2(hB, w3b, acc[2][3]);
                hA = pk2(h3.x, h3.y); hB = pk2(h3.z, h3.w);
                acc[3][0] = ffma2(hA, w0a, acc[3][0]); acc[3][0] = ffma2(hB, w0b, acc[3][0]);
                acc[3][1] = ffma2(hA, w1a, acc[3][1]); acc[3][1] = ffma2(hB, w1b, acc[3][1]);
                acc[3][2] = ffma2(hA, w2a, acc[3][2]); acc[3][2] = ffma2(hB, w2b, acc[3][2]);
                acc[3][3] = ffma2(hA, w3a, acc[3][3]); acc[3][3] = ffma2(hB, w3b, acc[3][3]);
            }

            // fold halves, write partials: pex[(ks*16 + b)][hcl*4 + g]
#pragma unroll
            for (int j = 0; j < 4; j++) {
                float2 v0 = upk2(acc[j][0]), v1 = upk2(acc[j][1]);
                float2 v2 = upk2(acc[j][2]), v3 = upk2(acc[j][3]);
                float4 pv = { v0.x + v0.y, v1.x + v1.y, v2.x + v2.y, v3.x + v3.y };
                int b = bq4 + 4 * j;
                *(float4*)&pex[(ks * 16 + b) * PEXR + hcl * 4] = pv;
            }
            __syncthreads();
        }

        // ---- reduction + elementwise + store (tid < 256) ----
        if (tid < 256) {
            float g0 = xv0, g1 = xv1, g2 = xv2, g3 = xv3;
            if (t > 0) {
#pragma unroll
                for (int q = 0; q < 8; q++) {
                    float4 pv = *(const float4*)&pex[(q * 16 + eb) * PEXR + ehcl * 4];
                    g0 += pv.x; g1 += pv.y; g2 += pv.z; g3 += pv.w;
                }
            }
            float iv = sigf(g0);
            float fv = sigf(g1);
            float gv = tanhx(g2);
            float ov = sigf(g3);
            cst = fv * cst + iv * gv;
            float hv = ov * tanhx(cst);
            ho[eb * 16 + ehcl] = hv;
            asm volatile("bar.sync 10, 256;" ::: "memory");
            if (tid < 64) {
                int row = tid >> 2, f4 = tid & 3;
                float4 v = ((const float4*)(ho + row * 16))[f4];
                *(float4*)&out[(size_t)t * (Bq * Hq) + (size_t)(b0 + row) * Hq + hc0 + f4 * 4] = v;
                asm volatile("bar.sync 11, 64;" ::: "memory");
                if (tid == 0 && t < Tq - 1) {
                    unsigned old;
                    asm volatile("atom.release.gpu.add.u32 %0, [%1], 1;"
                                 : "=r"(old) : "l"(cnt) : "memory");
                }
            }
        }
    }

    // final arrive; last CTA of the group resets its counter (replay-safe)
    if (tid == 0) {
        unsigned old;
        asm volatile("atom.release.gpu.add.u32 %0, [%1], 1;"
                     : "=r"(old) : "l"(cnt) : "memory");
        if (old == 32u * (unsigned)Tq - 1u)
            *((volatile unsigned*)cnt) = 0u;
    }
}

#define REC_SMEM ((64 * WSTR + 16 * WSTR + 128 * PEXR + 256) * 4)

extern "C" void kernel_launch(void* const* d_in, const int* in_sizes, int n_in,
                              void* d_out, int out_size) {
    const float* x   = (const float*)d_in[0];   // [512,64,512]
    const float* Wih = (const float*)d_in[1];   // [2048,512]
    const float* Whh = (const float*)d_in[2];   // [2048,512]
    const float* bih = (const float*)d_in[3];   // [2048]
    const float* bhh = (const float*)d_in[4];   // [2048]
    float* out = (float*)d_out;                 // [512,64,512]

    cudaFuncSetAttribute(lstm_rec, cudaFuncAttributeMaxDynamicSharedMemorySize, REC_SMEM);

    dim3 g1(G4 / 128, (Tq * Bq) / 128);         // (16, 256)
    gemm_xproj<<<g1, 256>>>(x, Wih, bih, bhh);
    lstm_rec<<<128, 512, REC_SMEM>>>(Whh, out);
}

// round 8
// speedup vs baseline: 2.1281x; 1.1883x over previous
#include <cuda_runtime.h>
#include <cuda_bf16.h>
#include <math.h>

// LSTM: T=512, B=64, I=H=512.  out[t,b,h] = h_t.
// Stage A: convert x, W_ih to split-bf16 (hi+lo) in m16n8k16 fragment order.
// Stage B: HMMA (mma.sync bf16, 3-pass split) -> x_proj[t][n][b] + bias.
// Stage C: persistent fp32 recurrence (R4-best, unchanged).

#define Tq 512
#define Bq 64
#define Hq 512
#define G4 2048
#define WSTR 516
#define PEXR 72
#define EPIR 132
#define AF4 2097152u             // uint4 count of A-hi region (2048*32*32)
#define WF2 262144u              // uint2 count of W-hi region (256*32*32)

typedef unsigned long long ull;

__device__ float g_xp[(size_t)Tq * G4 * Bq];        // 256MB x_proj scratch
__device__ unsigned g_cnt[4 * 32];                  // per-group counters
__device__ uint4 g_af[2 * AF4];                     // A frags hi|lo (64MB)
__device__ uint2 g_wf[2 * WF2];                     // W frags hi|lo (4MB)

__device__ __forceinline__ ull pk2(float lo, float hi) {
    ull r; asm("mov.b64 %0, {%1, %2};" : "=l"(r) : "f"(lo), "f"(hi)); return r;
}
__device__ __forceinline__ float2 upk2(ull v) {
    float2 r; asm("mov.b64 {%0, %1}, %2;" : "=f"(r.x), "=f"(r.y) : "l"(v)); return r;
}
__device__ __forceinline__ ull ffma2(ull a, ull b, ull c) {
    ull d; asm("fma.rn.f32x2 %0, %1, %2, %3;" : "=l"(d) : "l"(a), "l"(b), "l"(c)); return d;
}
__device__ __forceinline__ void cpa16(void* s, const void* g) {
    unsigned sa = (unsigned)__cvta_generic_to_shared(s);
    asm volatile("cp.async.cg.shared.global [%0], [%1], 16;" :: "r"(sa), "l"(g));
}
__device__ __forceinline__ void cpcommit() { asm volatile("cp.async.commit_group;"); }
template <int N> __device__ __forceinline__ void cpwait() {
    asm volatile("cp.async.wait_group %0;" :: "n"(N));
}
__device__ __forceinline__ float sigf(float x) {
    return __fdividef(1.f, 1.f + __expf(-x));
}
__device__ __forceinline__ float tanhx(float x) {
    return __fdividef(2.f, 1.f + __expf(-2.f * x)) - 1.f;
}
// split one float2 into packed-bf16x2 hi and lo words
__device__ __forceinline__ void split2(float2 v, unsigned& hi, unsigned& lo) {
    __nv_bfloat16 hx = __float2bfloat16(v.x);
    __nv_bfloat16 hy = __float2bfloat16(v.y);
    __nv_bfloat16 lx = __float2bfloat16(v.x - __bfloat162float(hx));
    __nv_bfloat16 ly = __float2bfloat16(v.y - __bfloat162float(hy));
    hi = (unsigned)__bfloat16_as_ushort(hx) | ((unsigned)__bfloat16_as_ushort(hy) << 16);
    lo = (unsigned)__bfloat16_as_ushort(lx) | ((unsigned)__bfloat16_as_ushort(ly) << 16);
}
__device__ __forceinline__ void mma16816(float* c, uint4 a, unsigned b0, unsigned b1) {
    asm volatile(
        "mma.sync.aligned.m16n8k16.row.col.f32.bf16.bf16.f32 "
        "{%0,%1,%2,%3},{%4,%5,%6,%7},{%8,%9},{%0,%1,%2,%3};"
        : "+f"(c[0]), "+f"(c[1]), "+f"(c[2]), "+f"(c[3])
        : "r"(a.x), "r"(a.y), "r"(a.z), "r"(a.w), "r"(b0), "r"(b1));
}

// ---------------------------------------------------------------------------
// conv_a: A[32768, 512] fp32 -> fragment order [mf 2048][kc 32][lane 32] uint4
// a0=(gr,tc..+1) a1=(gr+8,tc) a2=(gr,tc+8) a3=(gr+8,tc+8); hi region then lo.
// ---------------------------------------------------------------------------
__global__ __launch_bounds__(256) void conv_a(const float* __restrict__ x) {
    unsigned idx = blockIdx.x * 256 + threadIdx.x;   // < 2097152
    int lane = idx & 31;
    int kc = (idx >> 5) & 31;
    int mf = idx >> 10;
    int gr = lane >> 2, tc = (lane & 3) * 2;
    const float* base = x + (size_t)(mf * 16 + gr) * 512 + kc * 16 + tc;
    float2 r0 = *(const float2*)(base);              // (gr, tc)
    float2 r1 = *(const float2*)(base + 8);          // (gr, tc+8)
    float2 r2 = *(const float2*)(base + 8 * 512);    // (gr+8, tc)
    float2 r3 = *(const float2*)(base + 8 * 512 + 8);
    uint4 hi, lo;
    split2(r0, hi.x, lo.x);
    split2(r2, hi.y, lo.y);
    split2(r1, hi.z, lo.z);
    split2(r3, hi.w, lo.w);
    unsigned o = (mf * 32 + kc) * 32 + lane;
    g_af[o] = hi;
    g_af[o + AF4] = lo;
}

// ---------------------------------------------------------------------------
// conv_w: W[2048, 512] -> fragment order [nf 256][kc 32][lane 32] uint2
// b0=(k=tc..+1, n=gr) b1=(k=tc+8..+9, n=gr); hi region then lo.
// ---------------------------------------------------------------------------
__global__ __launch_bounds__(256) void conv_w(const float* __restrict__ W) {
    unsigned idx = blockIdx.x * 256 + threadIdx.x;   // < 262144
    int lane = idx & 31;
    int kc = (idx >> 5) & 31;
    int nf = idx >> 10;
    int gr = lane >> 2, tc = (lane & 3) * 2;
    const float* base = W + (size_t)(nf * 8 + gr) * 512 + kc * 16 + tc;
    float2 r0 = *(const float2*)(base);
    float2 r1 = *(const float2*)(base + 8);
    uint2 hi, lo;
    split2(r0, hi.x, lo.x);
    split2(r1, hi.y, lo.y);
    unsigned o = (nf * 32 + kc) * 32 + lane;
    g_wf[o] = hi;
    g_wf[o + WF2] = lo;
}

// ---------------------------------------------------------------------------
// gemm_tc: C[32768, 2048] = A * W^T + bias via 3-pass split-bf16 HMMA.
// Grid (nt 16, mt 256); CTA 256 thr = 8 warps; warp = 16 rows x 128 cols.
// W frags double-buffered in smem (2x8KB); A frags direct LDG.
// Epilogue: smem transpose (aliases staging) -> g_xp[t][n][b] + bias.
// ---------------------------------------------------------------------------
#define GEMM_SMEM (128 * EPIR * 4 + 512)             // 68096

__global__ __launch_bounds__(256) void gemm_tc(
    const float* __restrict__ bih, const float* __restrict__ bhh)
{
    extern __shared__ __align__(16) char smx[];
    float* bs = (float*)(smx + 128 * EPIR * 4);      // 128 bias floats
    const int tid = threadIdx.x;
    const int warp = tid >> 5;
    const int lane = tid & 31;
    const int gr = lane >> 2, tc = (lane & 3) * 2;
    const int nt = blockIdx.x;                        // 0..15
    const int mt = blockIdx.y;                        // 0..255
    const int mf = mt * 8 + warp;

    if (tid < 128) bs[tid] = bih[nt * 128 + tid] + bhh[nt * 128 + tid];
    __syncthreads();

    float c[16][4];
#pragma unroll
    for (int nf = 0; nf < 16; nf++)
#pragma unroll
        for (int j = 0; j < 4; j++) c[nf][j] = 0.f;

    // W stage copy: 8KB = hi 4KB + lo 4KB; thread i -> nf=i>>4, 16B chunk i&15
    auto load_w = [&](int kc, int buf) {
        int nfg = nt * 16 + (tid >> 4);
        int l16 = tid & 15;
        const char* src = (const char*)g_wf + ((size_t)(nfg * 32 + kc) * 32) * 8 + l16 * 16;
        char* dst = smx + buf * 8192 + (tid >> 4) * 256 + l16 * 16;
        cpa16(dst, src);
        cpa16(dst + 4096, src + (size_t)WF2 * 8);
        cpcommit();
    };

    uint4 ah = g_af[(mf * 32 + 0) * 32 + lane];
    uint4 al = g_af[(mf * 32 + 0) * 32 + lane + AF4];
    load_w(0, 0);
    load_w(1, 1);

#pragma unroll 1
    for (int kc = 0; kc < 32; kc++) {
        if (kc < 31) cpwait<1>(); else cpwait<0>();
        __syncthreads();
        uint4 ahn, aln;
        if (kc + 1 < 32) {
            ahn = g_af[(mf * 32 + kc + 1) * 32 + lane];
            aln = g_af[(mf * 32 + kc + 1) * 32 + lane + AF4];
        }
        const uint2* wh = (const uint2*)(smx + (kc & 1) * 8192);
        const uint2* wl = (const uint2*)(smx + (kc & 1) * 8192 + 4096);
#pragma unroll
        for (int nf = 0; nf < 16; nf++) {
            uint2 h = wh[nf * 32 + lane];
            uint2 l = wl[nf * 32 + lane];
            mma16816(c[nf], ah, h.x, h.y);
            mma16816(c[nf], al, h.x, h.y);
            mma16816(c[nf], ah, l.x, l.y);
        }
        __syncthreads();                      // buffer kc&1 fully consumed
        if (kc + 2 < 32) load_w(kc + 2, kc & 1);
        ah = ahn; al = aln;
    }

    // epilogue: frags -> smem [128 rows][EPIR], then coalesced b-major store
    __syncthreads();
    float* epi = (float*)smx;
#pragma unroll
    for (int nf = 0; nf < 16; nf++) {
        int col = nf * 8 + tc;
        *(float2*)&epi[(warp * 16 + gr) * EPIR + col] = make_float2(c[nf][0], c[nf][1]);
        *(float2*)&epi[(warp * 16 + gr + 8) * EPIR + col] = make_float2(c[nf][2], c[nf][3]);
    }
    __syncthreads();
    {
        int tloc = tid >> 7;                  // 0..1 (t within CTA's 128 rows)
        int n = tid & 127;
        float bv = bs[n];
        float* op = &g_xp[((size_t)(mt * 2 + tloc) * G4 + (size_t)nt * 128 + n) * Bq];
#pragma unroll
        for (int b4 = 0; b4 < 16; b4++) {
            const float* er = &epi[(tloc * 64 + b4 * 4) * EPIR + n];
            float4 v = make_float4(er[0 * EPIR] + bv, er[1 * EPIR] + bv,
                                   er[2 * EPIR] + bv, er[3 * EPIR] + bv);
            *(float4*)&op[b4 * 4] = v;
        }
    }
}

// ---------------------------------------------------------------------------
// Kernel: persistent recurrence (R4-best, unchanged).
// ---------------------------------------------------------------------------
__global__ __launch_bounds__(512, 1) void lstm_rec(
    const float* __restrict__ Whh, float* __restrict__ out)
{
    extern __shared__ float sm[];
    float* Ws = sm;
    float* hs = sm + 64 * WSTR;
    float* pex = hs + 16 * WSTR;
    float* ho = pex + 128 * PEXR;
    const int tid = threadIdx.x;
    const int bq4 = tid & 3;
    const int hcl = (tid >> 2) & 15;
    const int ks = tid >> 6;
    const int ks64 = ks * 64;
    const int bq = blockIdx.x >> 5;
    const int hg = blockIdx.x & 31;
    const int b0 = bq * 16;
    const int hc0 = hg * 16;
    const int eb = tid & 15;
    const int ehcl = (tid >> 4) & 15;
    unsigned* cnt = &g_cnt[bq * 32];

    for (int i = tid; i < 64 * 128; i += 512) {
        int r = i >> 7;
        int c4 = i & 127;
        int grow = (r >> 4) * 512 + hc0 + (r & 15);
        ((float4*)(Ws + r * WSTR))[c4] = ((const float4*)(Whh + (size_t)grow * 512))[c4];
    }
    __syncthreads();

    const float4* wp0 = (const float4*)(Ws + (0 * 16 + hcl) * WSTR + ks64);
    const float4* wp1 = (const float4*)(Ws + (1 * 16 + hcl) * WSTR + ks64);
    const float4* wp2 = (const float4*)(Ws + (2 * 16 + hcl) * WSTR + ks64);
    const float4* wp3 = (const float4*)(Ws + (3 * 16 + hcl) * WSTR + ks64);
    const float4* hq0 = (const float4*)(hs + (bq4 + 0) * WSTR + ks64);
    const float4* hq1 = (const float4*)(hs + (bq4 + 4) * WSTR + ks64);
    const float4* hq2 = (const float4*)(hs + (bq4 + 8) * WSTR + ks64);
    const float4* hq3 = (const float4*)(hs + (bq4 + 12) * WSTR + ks64);
    float cst = 0.f;

#pragma unroll 1
    for (int t = 0; t < Tq; t++) {
        float xv0, xv1, xv2, xv3;
        if (tid < 256) {
            const float* xpt = g_xp + (size_t)t * (G4 * Bq)
                             + (size_t)(hc0 + ehcl) * Bq + b0 + eb;
            xv0 = __ldg(xpt + 0 * 512 * Bq);
            xv1 = __ldg(xpt + 1 * 512 * Bq);
            xv2 = __ldg(xpt + 2 * 512 * Bq);
            xv3 = __ldg(xpt + 3 * 512 * Bq);
        }

        if (t > 0) {
            if (tid == 0) {
                unsigned tgt = 32u * (unsigned)t;
                unsigned v;
                do {
                    asm volatile("ld.acquire.gpu.u32 %0, [%1];"
                                 : "=r"(v) : "l"(cnt) : "memory");
                } while (v < tgt);
            }
            __syncthreads();

            const float* hp = out + (size_t)(t - 1) * (Bq * Hq) + (size_t)b0 * Hq;
            int l = tid & 63;
#pragma unroll
            for (int r = 0; r < 4; r++) {
                int j = l + r * 64;
                int row = j >> 4, kf = j & 15;
                cpa16(hs + row * WSTR + ks64 + kf * 4, hp + row * 512 + ks64 + kf * 4);
            }
            cpcommit();
            cpwait<0>();
            asm volatile("bar.sync %0, 64;" :: "r"(1 + ks) : "memory");

            ull acc[4][4];
#pragma unroll
            for (int j = 0; j < 4; j++)
#pragma unroll
                for (int g = 0; g < 4; g++) acc[j][g] = 0ull;

#pragma unroll 8
            for (int k4 = 0; k4 < 16; k4++) {
                float4 w0 = wp0[k4], w1 = wp1[k4], w2 = wp2[k4], w3 = wp3[k4];
                ull w0a = pk2(w0.x, w0.y), w0b = pk2(w0.z, w0.w);
                ull w1a = pk2(w1.x, w1.y), w1b = pk2(w1.z, w1.w);
                ull w2a = pk2(w2.x, w2.y), w2b = pk2(w2.z, w2.w);
                ull w3a = pk2(w3.x, w3.y), w3b = pk2(w3.z, w3.w);
                float4 h0 = hq0[k4], h1 = hq1[k4], h2 = hq2[k4], h3 = hq3[k4];
                ull hA, hB;
                hA = pk2(h0.x, h0.y); hB = pk2(h0.z, h0.w);
                acc[0][0] = ffma2(hA, w0a, acc[0][0]); acc[0][0] = ffma2(hB, w0b, acc[0][0]);
                acc[0][1] = ffma2(hA, w1a, acc[0][1]); acc[0][1] = ffma2(hB, w1b, acc[0][1]);
                acc[0][2] = ffma2(hA, w2a, acc[0][2]); acc[0][2] = ffma2(hB, w2b, acc[0][2]);
                acc[0][3] = ffma2(hA, w3a, acc[0][3]); acc[0][3] = ffma2(hB, w3b, acc[0][3]);
                hA = pk2(h1.x, h1.y); hB = pk2(h1.z, h1.w);
                acc[1][0] = ffma2(hA, w0a, acc[1][0]); acc[1][0] = ffma2(hB, w0b, acc[1][0]);
                acc[1][1] = ffma2(hA, w1a, acc[1][1]); acc[1][1] = ffma2(hB, w1b, acc[1][1]);
                acc[1][2] = ffma2(hA, w2a, acc[1][2]); acc[1][2] = ffma2(hB, w2b, acc[1][2]);
                acc[1][3] = ffma2(hA, w3a, acc[1][3]); acc[1][3] = ffma2(hB, w3b, acc[1][3]);
                hA = pk2(h2.x, h2.y); hB = pk2(h2.z, h2.w);
                acc[2][0] = ffma2(hA, w0a, acc[2][0]); acc[2][0] = ffma2(hB, w0b, acc[2][0]);
                acc[2][1] = ffma2(hA, w1a, acc[2][1]); acc[2][1] = ffma2(hB, w1b, acc[2][1]);
                acc[2][2] = ffma2(hA, w2a, acc[2][2]); acc[2][2] = ffma2(hB, w2b, acc[2][2]);
                acc[2][3] = ffma2(hA, w3a, acc[2][3]); acc[2][3] = ffma2(hB, w3b, acc[2][3]);
                hA = pk2(h3.x, h3.y); hB = pk2(h3.z, h3.w);
                acc[3][0] = ffma2(hA, w0a, acc[3][0]); acc[3][0] = ffma2(hB, w0b, acc[3][0]);
                acc[3][1] = ffma2(hA, w1a, acc[3][1]); acc[3][1] = ffma2(hB, w1b, acc[3][1]);
                acc[3][2] = ffma2(hA, w2a, acc[3][2]); acc[3][2] = ffma2(hB, w2b, acc[3][2]);
                acc[3][3] = ffma2(hA, w3a, acc[3][3]); acc[3][3] = ffma2(hB, w3b, acc[3][3]);
            }

#pragma unroll
            for (int j = 0; j < 4; j++) {
                float2 v0 = upk2(acc[j][0]), v1 = upk2(acc[j][1]);
                float2 v2 = upk2(acc[j][2]), v3 = upk2(acc[j][3]);
                float4 pv = { v0.x + v0.y, v1.x + v1.y, v2.x + v2.y, v3.x + v3.y };
                int b = bq4 + 4 * j;
                *(float4*)&pex[(ks * 16 + b) * PEXR + hcl * 4] = pv;
            }
            __syncthreads();
        }

        if (tid < 256) {
            float g0 = xv0, g1 = xv1, g2 = xv2, g3 = xv3;
            if (t > 0) {
#pragma unroll
                for (int q = 0; q < 8; q++) {
                    float4 pv = *(const float4*)&pex[(q * 16 + eb) * PEXR + ehcl * 4];
                    g0 += pv.x; g1 += pv.y; g2 += pv.z; g3 += pv.w;
                }
            }
            float iv = sigf(g0);
            float fv = sigf(g1);
            float gv = tanhx(g2);
            float ov = sigf(g3);
            cst = fv * cst + iv * gv;
            float hv = ov * tanhx(cst);
            ho[eb * 16 + ehcl] = hv;
            asm volatile("bar.sync 10, 256;" ::: "memory");
            if (tid < 64) {
                int row = tid >> 2, f4 = tid & 3;
                float4 v = ((const float4*)(ho + row * 16))[f4];
                *(float4*)&out[(size_t)t * (Bq * Hq) + (size_t)(b0 + row) * Hq + hc0 + f4 * 4] = v;
                asm volatile("bar.sync 11, 64;" ::: "memory");
                if (tid == 0 && t < Tq - 1) {
                    unsigned old;
                    asm volatile("atom.release.gpu.add.u32 %0, [%1], 1;"
                                 : "=r"(old) : "l"(cnt) : "memory");
                }
            }
        }
    }

    if (tid == 0) {
        unsigned old;
        asm volatile("atom.release.gpu.add.u32 %0, [%1], 1;"
                     : "=r"(old) : "l"(cnt) : "memory");
        if (old == 32u * (unsigned)Tq - 1u)
            *((volatile unsigned*)cnt) = 0u;
    }
}

#define REC_SMEM ((64 * WSTR + 16 * WSTR + 128 * PEXR + 256) * 4)

extern "C" void kernel_launch(void* const* d_in, const int* in_sizes, int n_in,
                              void* d_out, int out_size) {
    const float* x   = (const float*)d_in[0];   // [512,64,512]
    const float* Wih = (const float*)d_in[1];   // [2048,512]
    const float* Whh = (const float*)d_in[2];   // [2048,512]
    const float* bih = (const float*)d_in[3];   // [2048]
    const float* bhh = (const float*)d_in[4];   // [2048]
    float* out = (float*)d_out;                 // [512,64,512]

    cudaFuncSetAttribute(lstm_rec, cudaFuncAttributeMaxDynamicSharedMemorySize, REC_SMEM);
    cudaFuncSetAttribute(gemm_tc, cudaFuncAttributeMaxDynamicSharedMemorySize, GEMM_SMEM);

    conv_a<<<8192, 256>>>(x);                   // 2097152 threads
    conv_w<<<1024, 256>>>(Wih);                 // 262144 threads
    gemm_tc<<<dim3(16, 256), 256, GEMM_SMEM>>>(bih, bhh);
    lstm_rec<<<128, 512, REC_SMEM>>>(Whh, out);
}

// round 9
// speedup vs baseline: 2.9705x; 1.3958x over previous
#include <cuda_runtime.h>
#include <cuda_bf16.h>
#include <math.h>

// LSTM: T=512, B=64, I=H=512.  out[t,b,h] = h_t.
// Stage A: convert x, W_ih to split-bf16 fragments (R8, unchanged).
// Stage B: HMMA GEMM -> x_proj (R8, unchanged).
// Stage C: persistent recurrence, NOW HMMA-based: W_hh pre-fragmented in smem,
//          h passed between steps as pre-assembled bf16 hi/lo A-fragments in
//          a parity-double-buffered global (g_hf).

#define Tq 512
#define Bq 64
#define Hq 512
#define G4 2048
#define EPIR 132
#define AF4 2097152u
#define WF2 262144u

typedef unsigned long long ull;

__device__ float g_xp[(size_t)Tq * G4 * Bq];        // 256MB x_proj scratch
__device__ unsigned g_cnt[4 * 32];                  // per-group counters
__device__ uint4 g_af[2 * AF4];                     // GEMM A frags hi|lo
__device__ uint2 g_wf[2 * WF2];                     // GEMM W frags hi|lo
__device__ uint4 g_hf[2 * 8192];                    // h frags [par][hi|lo][bq][kc][lane]

__device__ __forceinline__ void cpa16(void* s, const void* g) {
    unsigned sa = (unsigned)__cvta_generic_to_shared(s);
    asm volatile("cp.async.cg.shared.global [%0], [%1], 16;" :: "r"(sa), "l"(g));
}
__device__ __forceinline__ void cpcommit() { asm volatile("cp.async.commit_group;"); }
template <int N> __device__ __forceinline__ void cpwait() {
    asm volatile("cp.async.wait_group %0;" :: "n"(N));
}
__device__ __forceinline__ float sigf(float x) {
    return __fdividef(1.f, 1.f + __expf(-x));
}
__device__ __forceinline__ float tanhx(float x) {
    return __fdividef(2.f, 1.f + __expf(-2.f * x)) - 1.f;
}
__device__ __forceinline__ void split2(float2 v, unsigned& hi, unsigned& lo) {
    __nv_bfloat16 hx = __float2bfloat16(v.x);
    __nv_bfloat16 hy = __float2bfloat16(v.y);
    __nv_bfloat16 lx = __float2bfloat16(v.x - __bfloat162float(hx));
    __nv_bfloat16 ly = __float2bfloat16(v.y - __bfloat162float(hy));
    hi = (unsigned)__bfloat16_as_ushort(hx) | ((unsigned)__bfloat16_as_ushort(hy) << 16);
    lo = (unsigned)__bfloat16_as_ushort(lx) | ((unsigned)__bfloat16_as_ushort(ly) << 16);
}
__device__ __forceinline__ void mma16816(float* c, uint4 a, unsigned b0, unsigned b1) {
    asm volatile(
        "mma.sync.aligned.m16n8k16.row.col.f32.bf16.bf16.f32 "
        "{%0,%1,%2,%3},{%4,%5,%6,%7},{%8,%9},{%0,%1,%2,%3};"
        : "+f"(c[0]), "+f"(c[1]), "+f"(c[2]), "+f"(c[3])
        : "r"(a.x), "r"(a.y), "r"(a.z), "r"(a.w), "r"(b0), "r"(b1));
}

// ---------------------------------------------------------------------------
// conv_a / conv_w / gemm_tc : unchanged from R8 (validated).
// ---------------------------------------------------------------------------
__global__ __launch_bounds__(256) void conv_a(const float* __restrict__ x) {
    unsigned idx = blockIdx.x * 256 + threadIdx.x;
    int lane = idx & 31;
    int kc = (idx >> 5) & 31;
    int mf = idx >> 10;
    int gr = lane >> 2, tc = (lane & 3) * 2;
    const float* base = x + (size_t)(mf * 16 + gr) * 512 + kc * 16 + tc;
    float2 r0 = *(const float2*)(base);
    float2 r1 = *(const float2*)(base + 8);
    float2 r2 = *(const float2*)(base + 8 * 512);
    float2 r3 = *(const float2*)(base + 8 * 512 + 8);
    uint4 hi, lo;
    split2(r0, hi.x, lo.x);
    split2(r2, hi.y, lo.y);
    split2(r1, hi.z, lo.z);
    split2(r3, hi.w, lo.w);
    unsigned o = (mf * 32 + kc) * 32 + lane;
    g_af[o] = hi;
    g_af[o + AF4] = lo;
}

__global__ __launch_bounds__(256) void conv_w(const float* __restrict__ W) {
    unsigned idx = blockIdx.x * 256 + threadIdx.x;
    int lane = idx & 31;
    int kc = (idx >> 5) & 31;
    int nf = idx >> 10;
    int gr = lane >> 2, tc = (lane & 3) * 2;
    const float* base = W + (size_t)(nf * 8 + gr) * 512 + kc * 16 + tc;
    float2 r0 = *(const float2*)(base);
    float2 r1 = *(const float2*)(base + 8);
    uint2 hi, lo;
    split2(r0, hi.x, lo.x);
    split2(r1, hi.y, lo.y);
    unsigned o = (nf * 32 + kc) * 32 + lane;
    g_wf[o] = hi;
    g_wf[o + WF2] = lo;
}

#define GEMM_SMEM (128 * EPIR * 4 + 512)

__global__ __launch_bounds__(256) void gemm_tc(
    const float* __restrict__ bih, const float* __restrict__ bhh)
{
    extern __shared__ __align__(16) char smx[];
    float* bs = (float*)(smx + 128 * EPIR * 4);
    const int tid = threadIdx.x;
    const int warp = tid >> 5;
    const int lane = tid & 31;
    const int gr = lane >> 2, tc = (lane & 3) * 2;
    const int nt = blockIdx.x;
    const int mt = blockIdx.y;
    const int mf = mt * 8 + warp;

    if (tid < 128) bs[tid] = bih[nt * 128 + tid] + bhh[nt * 128 + tid];
    __syncthreads();

    float c[16][4];
#pragma unroll
    for (int nf = 0; nf < 16; nf++)
#pragma unroll
        for (int j = 0; j < 4; j++) c[nf][j] = 0.f;

    auto load_w = [&](int kc, int buf) {
        int nfg = nt * 16 + (tid >> 4);
        int l16 = tid & 15;
        const char* src = (const char*)g_wf + ((size_t)(nfg * 32 + kc) * 32) * 8 + l16 * 16;
        char* dst = smx + buf * 8192 + (tid >> 4) * 256 + l16 * 16;
        cpa16(dst, src);
        cpa16(dst + 4096, src + (size_t)WF2 * 8);
        cpcommit();
    };

    uint4 ah = g_af[(mf * 32 + 0) * 32 + lane];
    uint4 al = g_af[(mf * 32 + 0) * 32 + lane + AF4];
    load_w(0, 0);
    load_w(1, 1);

#pragma unroll 1
    for (int kc = 0; kc < 32; kc++) {
        if (kc < 31) cpwait<1>(); else cpwait<0>();
        __syncthreads();
        uint4 ahn, aln;
        if (kc + 1 < 32) {
            ahn = g_af[(mf * 32 + kc + 1) * 32 + lane];
            aln = g_af[(mf * 32 + kc + 1) * 32 + lane + AF4];
        }
        const uint2* wh = (const uint2*)(smx + (kc & 1) * 8192);
        const uint2* wl = (const uint2*)(smx + (kc & 1) * 8192 + 4096);
#pragma unroll
        for (int nf = 0; nf < 16; nf++) {
            uint2 h = wh[nf * 32 + lane];
            uint2 l = wl[nf * 32 + lane];
            mma16816(c[nf], ah, h.x, h.y);
            mma16816(c[nf], al, h.x, h.y);
            mma16816(c[nf], ah, l.x, l.y);
        }
        __syncthreads();
        if (kc + 2 < 32) load_w(kc + 2, kc & 1);
        ah = ahn; al = aln;
    }

    __syncthreads();
    float* epi = (float*)smx;
#pragma unroll
    for (int nf = 0; nf < 16; nf++) {
        int col = nf * 8 + tc;
        *(float2*)&epi[(warp * 16 + gr) * EPIR + col] = make_float2(c[nf][0], c[nf][1]);
        *(float2*)&epi[(warp * 16 + gr + 8) * EPIR + col] = make_float2(c[nf][2], c[nf][3]);
    }
    __syncthreads();
    {
        int tloc = tid >> 7;
        int n = tid & 127;
        float bv = bs[n];
        float* op = &g_xp[((size_t)(mt * 2 + tloc) * G4 + (size_t)nt * 128 + n) * Bq];
#pragma unroll
        for (int b4 = 0; b4 < 16; b4++) {
            const float* er = &epi[(tloc * 64 + b4 * 4) * EPIR + n];
            float4 v = make_float4(er[0 * EPIR] + bv, er[1 * EPIR] + bv,
                                   er[2 * EPIR] + bv, er[3 * EPIR] + bv);
            *(float4*)&op[b4 * 4] = v;
        }
    }
}

// ---------------------------------------------------------------------------
// lstm_rec: persistent HMMA recurrence. grid 128 = (bq 4) x (hg 32), 512 thr.
// smem: W_hh B-frags hi/lo (128KB, built once), h A-frag stage (32KB),
//       pex C-reduction, ho/hbl producer staging.
// MMA: warp w -> nf = w&7 (8 gate cols), kh = w>>3 (K half), 48 MMAs/step.
// h handoff: warp0 assembles A-frags (bf16 hi/lo) -> g_hf[(t+1)&1][bq][hg].
// ---------------------------------------------------------------------------
#define OFF_WF_LO 65536
#define OFF_HF    131072
#define OFF_HF_LO 147456
#define OFF_PEX   163840
#define OFF_HO    172544
#define OFF_HBL   173568
#define REC_SMEM  174848

__global__ __launch_bounds__(512, 1) void lstm_rec(
    const float* __restrict__ Whh, float* __restrict__ out)
{
    extern __shared__ __align__(16) char smc[];
    uint2* wfHI = (uint2*)(smc);
    uint2* wfLO = (uint2*)(smc + OFF_WF_LO);
    uint4* hfHI = (uint4*)(smc + OFF_HF);
    uint4* hfLO = (uint4*)(smc + OFF_HF_LO);
    float* pex = (float*)(smc + OFF_PEX);           // [2*16 rows][68]
    float* ho = (float*)(smc + OFF_HO);             // [16 b][16 hc]
    unsigned* hbl = (unsigned*)(smc + OFF_HBL);     // [16 kk][17] hi|lo<<16

    const int tid = threadIdx.x;
    const int warp = tid >> 5;
    const int lane = tid & 31;
    const int bq = blockIdx.x >> 5;
    const int hg = blockIdx.x & 31;
    const int b0 = bq * 16;
    const int hc0 = hg * 16;
    const int eb = tid & 15;
    const int ehcl = (tid >> 4) & 15;
    const int nf = warp & 7;
    const int kh = warp >> 3;
    unsigned* cnt = &g_cnt[bq * 32];

    // ---- build W_hh B-fragments once: local col c = hcl*4+g = nf*8+gr ----
    for (int idx = tid; idx < 8192; idx += 512) {
        int l = idx & 31, nfi = (idx >> 5) & 7, kc = idx >> 8;
        int gr = l >> 2, tc2 = (l & 3) * 2;
        int c = nfi * 8 + gr;
        int grow = (c & 3) * 512 + hc0 + (c >> 2);
        const float* wb = Whh + (size_t)grow * 512 + kc * 16 + tc2;
        float2 r0 = *(const float2*)wb;
        float2 r1 = *(const float2*)(wb + 8);
        unsigned h0, l0, h1, l1;
        split2(r0, h0, l0);
        split2(r1, h1, l1);
        wfHI[(kc * 8 + nfi) * 32 + l] = make_uint2(h0, h1);
        wfLO[(kc * 8 + nfi) * 32 + l] = make_uint2(l0, l1);
    }
    __syncthreads();

    float cst = 0.f;

#pragma unroll 1
    for (int t = 0; t < Tq; t++) {
        float xv0 = 0.f, xv1 = 0.f, xv2 = 0.f, xv3 = 0.f;
        if (tid < 256) {
            const float* xpt = g_xp + (size_t)t * (G4 * Bq)
                             + (size_t)(hc0 + ehcl) * Bq + b0 + eb;
            xv0 = __ldg(xpt + 0 * 512 * Bq);
            xv1 = __ldg(xpt + 1 * 512 * Bq);
            xv2 = __ldg(xpt + 2 * 512 * Bq);
            xv3 = __ldg(xpt + 3 * 512 * Bq);
        }

        if (t > 0) {
            // ---- group barrier: h frags of step t-1 ready ----
            if (tid == 0) {
                unsigned tgt = 32u * (unsigned)t;
                unsigned v;
                do {
                    asm volatile("ld.acquire.gpu.u32 %0, [%1];"
                                 : "=r"(v) : "l"(cnt) : "memory");
                } while (v < tgt);
            }
            __syncthreads();

            // ---- stage 32KB of A-fragments (hi+lo) from g_hf[t&1][bq] ----
            {
                const char* gH = (const char*)(g_hf + (size_t)(t & 1) * 8192 + bq * 1024);
                const char* gL = (const char*)(g_hf + (size_t)(t & 1) * 8192 + 4096 + bq * 1024);
#pragma unroll
                for (int j = 0; j < 2; j++) {
                    int idx = tid + j * 512;
                    cpa16((char*)hfHI + idx * 16, gH + idx * 16);
                    cpa16((char*)hfLO + idx * 16, gL + idx * 16);
                }
                cpcommit();
                cpwait<0>();
                __syncthreads();
            }

            // ---- MMA: 16 kc per warp, 3 passes ----
            float cc[4] = { 0.f, 0.f, 0.f, 0.f };
#pragma unroll 4
            for (int kc16 = 0; kc16 < 16; kc16++) {
                int kc = kh * 16 + kc16;
                uint4 ah = hfHI[kc * 32 + lane];
                uint4 al = hfLO[kc * 32 + lane];
                uint2 wh = wfHI[(kc * 8 + nf) * 32 + lane];
                uint2 wl = wfLO[(kc * 8 + nf) * 32 + lane];
                mma16816(cc, ah, wh.x, wh.y);
                mma16816(cc, al, wh.x, wh.y);
                mma16816(cc, ah, wl.x, wl.y);
            }
            {
                int gr = lane >> 2, tc2 = (lane & 3) * 2;
                int col = nf * 8 + tc2;
                *(float2*)&pex[(kh * 16 + gr) * 68 + col] = make_float2(cc[0], cc[1]);
                *(float2*)&pex[(kh * 16 + gr + 8) * 68 + col] = make_float2(cc[2], cc[3]);
            }
            __syncthreads();
        }

        // ---- reduction + elementwise + h handoff (tid < 256) ----
        if (tid < 256) {
            float g0 = xv0, g1 = xv1, g2 = xv2, g3 = xv3;
            if (t > 0) {
                float4 p0 = *(const float4*)&pex[eb * 68 + ehcl * 4];
                float4 p1 = *(const float4*)&pex[(16 + eb) * 68 + ehcl * 4];
                g0 += p0.x + p1.x;
                g1 += p0.y + p1.y;
                g2 += p0.z + p1.z;
                g3 += p0.w + p1.w;
            }
            float iv = sigf(g0);
            float fv = sigf(g1);
            float gv = tanhx(g2);
            float ov = sigf(g3);
            cst = fv * cst + iv * gv;
            float hv = ov * tanhx(cst);

            ho[eb * 16 + ehcl] = hv;
            // bf16 split pack: hi | lo<<16, indexed [kk=ehcl][b=eb]
            {
                __nv_bfloat16 hh = __float2bfloat16(hv);
                __nv_bfloat16 hl = __float2bfloat16(hv - __bfloat162float(hh));
                hbl[ehcl * 17 + eb] = (unsigned)__bfloat16_as_ushort(hh)
                                    | ((unsigned)__bfloat16_as_ushort(hl) << 16);
            }
            asm volatile("bar.sync 10, 256;" ::: "memory");

            if (tid < 128) {
                if (tid < 32 && t < Tq - 1) {
                    // warp0: assemble A-fragment words, write g_hf[(t+1)&1]
                    int gr = lane >> 2;
                    int k0 = (lane & 3) * 2;
                    unsigned x0 = hbl[k0 * 17 + gr],        x1 = hbl[(k0 + 1) * 17 + gr];
                    unsigned y0 = hbl[k0 * 17 + gr + 8],    y1 = hbl[(k0 + 1) * 17 + gr + 8];
                    unsigned z0 = hbl[(k0 + 8) * 17 + gr],  z1 = hbl[(k0 + 9) * 17 + gr];
                    unsigned w0 = hbl[(k0 + 8) * 17 + gr + 8], w1 = hbl[(k0 + 9) * 17 + gr + 8];
                    uint4 hi = make_uint4(__byte_perm(x0, x1, 0x5410),
                                          __byte_perm(y0, y1, 0x5410),
                                          __byte_perm(z0, z1, 0x5410),
                                          __byte_perm(w0, w1, 0x5410));
                    uint4 lo = make_uint4(__byte_perm(x0, x1, 0x7632),
                                          __byte_perm(y0, y1, 0x7632),
                                          __byte_perm(z0, z1, 0x7632),
                                          __byte_perm(w0, w1, 0x7632));
                    size_t base = (size_t)((t + 1) & 1) * 8192 + (bq * 32 + hg) * 32 + lane;
                    g_hf[base] = hi;
                    g_hf[base + 4096] = lo;
                } else if (tid >= 64) {
                    // warps 2,3: coalesced fp32 h store to out
                    int row = (tid - 64) >> 2, f4 = (tid - 64) & 3;
                    float4 v = ((const float4*)(ho + row * 16))[f4];
                    *(float4*)&out[(size_t)t * (Bq * Hq) + (size_t)(b0 + row) * Hq
                                   + hc0 + f4 * 4] = v;
                }
                asm volatile("bar.sync 11, 128;" ::: "memory");
                if (tid == 0 && t < Tq - 1) {
                    unsigned old;
                    asm volatile("atom.release.gpu.add.u32 %0, [%1], 1;"
                                 : "=r"(old) : "l"(cnt) : "memory");
                }
            }
        }
    }

    // final arrive; last CTA of the group resets its counter (replay-safe)
    if (tid == 0) {
        unsigned old;
        asm volatile("atom.release.gpu.add.u32 %0, [%1], 1;"
                     : "=r"(old) : "l"(cnt) : "memory");
        if (old == 32u * (unsigned)Tq - 1u)
            *((volatile unsigned*)cnt) = 0u;
    }
}

extern "C" void kernel_launch(void* const* d_in, const int* in_sizes, int n_in,
                              void* d_out, int out_size) {
    const float* x   = (const float*)d_in[0];   // [512,64,512]
    const float* Wih = (const float*)d_in[1];   // [2048,512]
    const float* Whh = (const float*)d_in[2];   // [2048,512]
    const float* bih = (const float*)d_in[3];   // [2048]
    const float* bhh = (const float*)d_in[4];   // [2048]
    float* out = (float*)d_out;                 // [512,64,512]

    cudaFuncSetAttribute(lstm_rec, cudaFuncAttributeMaxDynamicSharedMemorySize, REC_SMEM);
    cudaFuncSetAttribute(gemm_tc, cudaFuncAttributeMaxDynamicSharedMemorySize, GEMM_SMEM);

    conv_a<<<8192, 256>>>(x);
    conv_w<<<1024, 256>>>(Wih);
    gemm_tc<<<dim3(16, 256), 256, GEMM_SMEM>>>(bih, bhh);
    lstm_rec<<<128, 512, REC_SMEM>>>(Whh, out);
}

// round 10
// speedup vs baseline: 2.9892x; 1.0063x over previous
#include <cuda_runtime.h>
#include <cuda_bf16.h>
#include <math.h>

// LSTM: T=512, B=64, I=H=512.  out[t,b,h] = h_t.
// Stage A: convert x, W_ih to split-bf16 fragments (R8, unchanged).
// Stage B: HMMA GEMM -> x_proj (R8, unchanged).
// Stage C: persistent HMMA recurrence; R9 + split-half staging + early release.

#define Tq 512
#define Bq 64
#define Hq 512
#define G4 2048
#define EPIR 132
#define AF4 2097152u
#define WF2 262144u

typedef unsigned long long ull;

__device__ float g_xp[(size_t)Tq * G4 * Bq];        // 256MB x_proj scratch
__device__ unsigned g_cnt[4 * 32];                  // per-group counters
__device__ uint4 g_af[2 * AF4];                     // GEMM A frags hi|lo
__device__ uint2 g_wf[2 * WF2];                     // GEMM W frags hi|lo
__device__ uint4 g_hf[2 * 8192];                    // h frags [par][hi|lo][bq][kc][lane]

__device__ __forceinline__ void cpa16(void* s, const void* g) {
    unsigned sa = (unsigned)__cvta_generic_to_shared(s);
    asm volatile("cp.async.cg.shared.global [%0], [%1], 16;" :: "r"(sa), "l"(g));
}
__device__ __forceinline__ void cpcommit() { asm volatile("cp.async.commit_group;"); }
template <int N> __device__ __forceinline__ void cpwait() {
    asm volatile("cp.async.wait_group %0;" :: "n"(N));
}
__device__ __forceinline__ float sigf(float x) {
    return __fdividef(1.f, 1.f + __expf(-x));
}
__device__ __forceinline__ float tanhx(float x) {
    return __fdividef(2.f, 1.f + __expf(-2.f * x)) - 1.f;
}
__device__ __forceinline__ void split2(float2 v, unsigned& hi, unsigned& lo) {
    __nv_bfloat16 hx = __float2bfloat16(v.x);
    __nv_bfloat16 hy = __float2bfloat16(v.y);
    __nv_bfloat16 lx = __float2bfloat16(v.x - __bfloat162float(hx));
    __nv_bfloat16 ly = __float2bfloat16(v.y - __bfloat162float(hy));
    hi = (unsigned)__bfloat16_as_ushort(hx) | ((unsigned)__bfloat16_as_ushort(hy) << 16);
    lo = (unsigned)__bfloat16_as_ushort(lx) | ((unsigned)__bfloat16_as_ushort(ly) << 16);
}
__device__ __forceinline__ void mma16816(float* c, uint4 a, unsigned b0, unsigned b1) {
    asm volatile(
        "mma.sync.aligned.m16n8k16.row.col.f32.bf16.bf16.f32 "
        "{%0,%1,%2,%3},{%4,%5,%6,%7},{%8,%9},{%0,%1,%2,%3};"
        : "+f"(c[0]), "+f"(c[1]), "+f"(c[2]), "+f"(c[3])
        : "r"(a.x), "r"(a.y), "r"(a.z), "r"(a.w), "r"(b0), "r"(b1));
}

// ---------------------------------------------------------------------------
// conv_a / conv_w / gemm_tc : unchanged from R8 (validated).
// ---------------------------------------------------------------------------
__global__ __launch_bounds__(256) void conv_a(const float* __restrict__ x) {
    unsigned idx = blockIdx.x * 256 + threadIdx.x;
    int lane = idx & 31;
    int kc = (idx >> 5) & 31;
    int mf = idx >> 10;
    int gr = lane >> 2, tc = (lane & 3) * 2;
    const float* base = x + (size_t)(mf * 16 + gr) * 512 + kc * 16 + tc;
    float2 r0 = *(const float2*)(base);
    float2 r1 = *(const float2*)(base + 8);
    float2 r2 = *(const float2*)(base + 8 * 512);
    float2 r3 = *(const float2*)(base + 8 * 512 + 8);
    uint4 hi, lo;
    split2(r0, hi.x, lo.x);
    split2(r2, hi.y, lo.y);
    split2(r1, hi.z, lo.z);
    split2(r3, hi.w, lo.w);
    unsigned o = (mf * 32 + kc) * 32 + lane;
    g_af[o] = hi;
    g_af[o + AF4] = lo;
}

__global__ __launch_bounds__(256) void conv_w(const float* __restrict__ W) {
    unsigned idx = blockIdx.x * 256 + threadIdx.x;
    int lane = idx & 31;
    int kc = (idx >> 5) & 31;
    int nf = idx >> 10;
    int gr = lane >> 2, tc = (lane & 3) * 2;
    const float* base = W + (size_t)(nf * 8 + gr) * 512 + kc * 16 + tc;
    float2 r0 = *(const float2*)(base);
    float2 r1 = *(const float2*)(base + 8);
    uint2 hi, lo;
    split2(r0, hi.x, lo.x);
    split2(r1, hi.y, lo.y);
    unsigned o = (nf * 32 + kc) * 32 + lane;
    g_wf[o] = hi;
    g_wf[o + WF2] = lo;
}

#define GEMM_SMEM (128 * EPIR * 4 + 512)

__global__ __launch_bounds__(256) void gemm_tc(
    const float* __restrict__ bih, const float* __restrict__ bhh)
{
    extern __shared__ __align__(16) char smx[];
    float* bs = (float*)(smx + 128 * EPIR * 4);
    const int tid = threadIdx.x;
    const int warp = tid >> 5;
    const int lane = tid & 31;
    const int gr = lane >> 2, tc = (lane & 3) * 2;
    const int nt = blockIdx.x;
    const int mt = blockIdx.y;
    const int mf = mt * 8 + warp;

    if (tid < 128) bs[tid] = bih[nt * 128 + tid] + bhh[nt * 128 + tid];
    __syncthreads();

    float c[16][4];
#pragma unroll
    for (int nf = 0; nf < 16; nf++)
#pragma unroll
        for (int j = 0; j < 4; j++) c[nf][j] = 0.f;

    auto load_w = [&](int kc, int buf) {
        int nfg = nt * 16 + (tid >> 4);
        int l16 = tid & 15;
        const char* src = (const char*)g_wf + ((size_t)(nfg * 32 + kc) * 32) * 8 + l16 * 16;
        char* dst = smx + buf * 8192 + (tid >> 4) * 256 + l16 * 16;
        cpa16(dst, src);
        cpa16(dst + 4096, src + (size_t)WF2 * 8);
        cpcommit();
    };

    uint4 ah = g_af[(mf * 32 + 0) * 32 + lane];
    uint4 al = g_af[(mf * 32 + 0) * 32 + lane + AF4];
    load_w(0, 0);
    load_w(1, 1);

#pragma unroll 1
    for (int kc = 0; kc < 32; kc++) {
        if (kc < 31) cpwait<1>(); else cpwait<0>();
        __syncthreads();
        uint4 ahn, aln;
        if (kc + 1 < 32) {
            ahn = g_af[(mf * 32 + kc + 1) * 32 + lane];
            aln = g_af[(mf * 32 + kc + 1) * 32 + lane + AF4];
        }
        const uint2* wh = (const uint2*)(smx + (kc & 1) * 8192);
        const uint2* wl = (const uint2*)(smx + (kc & 1) * 8192 + 4096);
#pragma unroll
        for (int nf = 0; nf < 16; nf++) {
            uint2 h = wh[nf * 32 + lane];
            uint2 l = wl[nf * 32 + lane];
            mma16816(c[nf], ah, h.x, h.y);
            mma16816(c[nf], al, h.x, h.y);
            mma16816(c[nf], ah, l.x, l.y);
        }
        __syncthreads();
        if (kc + 2 < 32) load_w(kc + 2, kc & 1);
        ah = ahn; al = aln;
    }

    __syncthreads();
    float* epi = (float*)smx;
#pragma unroll
    for (int nf = 0; nf < 16; nf++) {
        int col = nf * 8 + tc;
        *(float2*)&epi[(warp * 16 + gr) * EPIR + col] = make_float2(c[nf][0], c[nf][1]);
        *(float2*)&epi[(warp * 16 + gr + 8) * EPIR + col] = make_float2(c[nf][2], c[nf][3]);
    }
    __syncthreads();
    {
        int tloc = tid >> 7;
        int n = tid & 127;
        float bv = bs[n];
        float* op = &g_xp[((size_t)(mt * 2 + tloc) * G4 + (size_t)nt * 128 + n) * Bq];
#pragma unroll
        for (int b4 = 0; b4 < 16; b4++) {
            const float* er = &epi[(tloc * 64 + b4 * 4) * EPIR + n];
            float4 v = make_float4(er[0 * EPIR] + bv, er[1 * EPIR] + bv,
                                   er[2 * EPIR] + bv, er[3 * EPIR] + bv);
            *(float4*)&op[b4 * 4] = v;
        }
    }
}

// ---------------------------------------------------------------------------
// lstm_rec: persistent HMMA recurrence. grid 128 = (bq 4) x (hg 32), 512 thr.
// R10 changes: (1) per-K-half staging behind named barriers (each half's 8
// warps start MMA after 16KB, not 32KB+syncthreads); (2) early cross-CTA
// release: warp0 STG h-frags + __syncwarp + lane0 atom.release, out-stores
// (warps 2-3) off the critical path.
// ---------------------------------------------------------------------------
#define OFF_WF_LO 65536
#define OFF_HF    131072
#define OFF_HF_LO 147456
#define OFF_PEX   163840
#define OFF_HO    172544
#define OFF_HBL   173568
#define REC_SMEM  174848

__global__ __launch_bounds__(512, 1) void lstm_rec(
    const float* __restrict__ Whh, float* __restrict__ out)
{
    extern __shared__ __align__(16) char smc[];
    uint2* wfHI = (uint2*)(smc);
    uint2* wfLO = (uint2*)(smc + OFF_WF_LO);
    uint4* hfHI = (uint4*)(smc + OFF_HF);
    uint4* hfLO = (uint4*)(smc + OFF_HF_LO);
    float* pex = (float*)(smc + OFF_PEX);           // [2*16 rows][68]
    float* ho = (float*)(smc + OFF_HO);             // [16 b][16 hc]
    unsigned* hbl = (unsigned*)(smc + OFF_HBL);     // [16 kk][17] hi|lo<<16

    const int tid = threadIdx.x;
    const int warp = tid >> 5;
    const int lane = tid & 31;
    const int bq = blockIdx.x >> 5;
    const int hg = blockIdx.x & 31;
    const int b0 = bq * 16;
    const int hc0 = hg * 16;
    const int eb = tid & 15;
    const int ehcl = (tid >> 4) & 15;
    const int nf = warp & 7;
    const int kh = warp >> 3;
    unsigned* cnt = &g_cnt[bq * 32];

    // ---- build W_hh B-fragments once: local col c = hcl*4+g = nf*8+gr ----
    for (int idx = tid; idx < 8192; idx += 512) {
        int l = idx & 31, nfi = (idx >> 5) & 7, kc = idx >> 8;
        int gr = l >> 2, tc2 = (l & 3) * 2;
        int c = nfi * 8 + gr;
        int grow = (c & 3) * 512 + hc0 + (c >> 2);
        const float* wb = Whh + (size_t)grow * 512 + kc * 16 + tc2;
        float2 r0 = *(const float2*)wb;
        float2 r1 = *(const float2*)(wb + 8);
        unsigned h0, l0, h1, l1;
        split2(r0, h0, l0);
        split2(r1, h1, l1);
        wfHI[(kc * 8 + nfi) * 32 + l] = make_uint2(h0, h1);
        wfLO[(kc * 8 + nfi) * 32 + l] = make_uint2(l0, l1);
    }
    __syncthreads();

    float cst = 0.f;

#pragma unroll 1
    for (int t = 0; t < Tq; t++) {
        float xv0 = 0.f, xv1 = 0.f, xv2 = 0.f, xv3 = 0.f;
        if (tid < 256) {
            const float* xpt = g_xp + (size_t)t * (G4 * Bq)
                             + (size_t)(hc0 + ehcl) * Bq + b0 + eb;
            xv0 = __ldg(xpt + 0 * 512 * Bq);
            xv1 = __ldg(xpt + 1 * 512 * Bq);
            xv2 = __ldg(xpt + 2 * 512 * Bq);
            xv3 = __ldg(xpt + 3 * 512 * Bq);
        }

        if (t > 0) {
            // ---- group barrier: h frags of step t-1 ready ----
            if (tid == 0) {
                unsigned tgt = 32u * (unsigned)t;
                unsigned v;
                do {
                    asm volatile("ld.acquire.gpu.u32 %0, [%1];"
                                 : "=r"(v) : "l"(cnt) : "memory");
                } while (v < tgt);
            }
            __syncthreads();

            // ---- per-half staging: my half (kh) stages its 16KB, own bar ----
            {
                const char* gB = (const char*)g_hf + (size_t)(t & 1) * 131072
                               + bq * 16384 + kh * 8192;
                char* sH = (char*)hfHI + kh * 8192;
                char* sL = (char*)hfLO + kh * 8192;
                int l = tid & 255;
                cpa16(sH + l * 16, gB + l * 16);
                cpa16(sH + (l + 256) * 16, gB + (l + 256) * 16);
                cpa16(sL + l * 16, gB + 65536 + l * 16);
                cpa16(sL + (l + 256) * 16, gB + 65536 + (l + 256) * 16);
                cpcommit();
                cpwait<0>();
                asm volatile("bar.sync %0, 256;" :: "r"(1 + kh) : "memory");
            }

            // ---- MMA: 16 kc per warp, 3 passes ----
            float cc[4] = { 0.f, 0.f, 0.f, 0.f };
#pragma unroll 4
            for (int kc16 = 0; kc16 < 16; kc16++) {
                int kc = kh * 16 + kc16;
                uint4 ah = hfHI[kc * 32 + lane];
                uint4 al = hfLO[kc * 32 + lane];
                uint2 wh = wfHI[(kc * 8 + nf) * 32 + lane];
                uint2 wl = wfLO[(kc * 8 + nf) * 32 + lane];
                mma16816(cc, ah, wh.x, wh.y);
                mma16816(cc, al, wh.x, wh.y);
                mma16816(cc, ah, wl.x, wl.y);
            }
            {
                int gr = lane >> 2, tc2 = (lane & 3) * 2;
                int col = nf * 8 + tc2;
                *(float2*)&pex[(kh * 16 + gr) * 68 + col] = make_float2(cc[0], cc[1]);
                *(float2*)&pex[(kh * 16 + gr + 8) * 68 + col] = make_float2(cc[2], cc[3]);
            }
            __syncthreads();
        }

        // ---- reduction + elementwise + h handoff (tid < 256) ----
        if (tid < 256) {
            float g0 = xv0, g1 = xv1, g2 = xv2, g3 = xv3;
            if (t > 0) {
                float4 p0 = *(const float4*)&pex[eb * 68 + ehcl * 4];
                float4 p1 = *(const float4*)&pex[(16 + eb) * 68 + ehcl * 4];
                g0 += p0.x + p1.x;
                g1 += p0.y + p1.y;
                g2 += p0.z + p1.z;
                g3 += p0.w + p1.w;
            }
            float iv = sigf(g0);
            float fv = sigf(g1);
            float gv = tanhx(g2);
            float ov = sigf(g3);
            cst = fv * cst + iv * gv;
            float hv = ov * tanhx(cst);

            ho[eb * 16 + ehcl] = hv;
            // bf16 split pack: hi | lo<<16, indexed [kk=ehcl][b=eb]
            {
                __nv_bfloat16 hh = __float2bfloat16(hv);
                __nv_bfloat16 hl = __float2bfloat16(hv - __bfloat162float(hh));
                hbl[ehcl * 17 + eb] = (unsigned)__bfloat16_as_ushort(hh)
                                    | ((unsigned)__bfloat16_as_ushort(hl) << 16);
            }
            asm volatile("bar.sync 10, 256;" ::: "memory");

            if (tid < 32) {
                // warp0: assemble A-fragment words, write g_hf, early release
                if (t < Tq - 1) {
                    int gr = lane >> 2;
                    int k0 = (lane & 3) * 2;
                    unsigned x0 = hbl[k0 * 17 + gr],        x1 = hbl[(k0 + 1) * 17 + gr];
                    unsigned y0 = hbl[k0 * 17 + gr + 8],    y1 = hbl[(k0 + 1) * 17 + gr + 8];
                    unsigned z0 = hbl[(k0 + 8) * 17 + gr],  z1 = hbl[(k0 + 9) * 17 + gr];
                    unsigned w0 = hbl[(k0 + 8) * 17 + gr + 8], w1 = hbl[(k0 + 9) * 17 + gr + 8];
                    uint4 hi = make_uint4(__byte_perm(x0, x1, 0x5410),
                                          __byte_perm(y0, y1, 0x5410),
                                          __byte_perm(z0, z1, 0x5410),
                                          __byte_perm(w0, w1, 0x5410));
                    uint4 lo = make_uint4(__byte_perm(x0, x1, 0x7632),
                                          __byte_perm(y0, y1, 0x7632),
                                          __byte_perm(z0, z1, 0x7632),
                                          __byte_perm(w0, w1, 0x7632));
                    size_t base = (size_t)((t + 1) & 1) * 8192 + (bq * 32 + hg) * 32 + lane;
                    g_hf[base] = hi;
                    g_hf[base + 4096] = lo;
                    __syncwarp();
                    if (lane == 0) {
                        unsigned old;
                        asm volatile("atom.release.gpu.add.u32 %0, [%1], 1;"
                                     : "=r"(old) : "l"(cnt) : "memory");
                    }
                }
            } else if (tid >= 64 && tid < 128) {
                // warps 2,3: coalesced fp32 h store to out (off critical path)
                int row = (tid - 64) >> 2, f4 = (tid - 64) & 3;
                float4 v = ((const float4*)(ho + row * 16))[f4];
                *(float4*)&out[(size_t)t * (Bq * Hq) + (size_t)(b0 + row) * Hq
                               + hc0 + f4 * 4] = v;
            }
        }
    }

    // final arrive; last CTA of the group resets its counter (replay-safe)
    if (tid == 0) {
        unsigned old;
        asm volatile("atom.release.gpu.add.u32 %0, [%1], 1;"
                     : "=r"(old) : "l"(cnt) : "memory");
        if (old == 32u * (unsigned)(Tq - 1) + 32u - 1u)
            *((volatile unsigned*)cnt) = 0u;
    }
}

extern "C" void kernel_launch(void* const* d_in, const int* in_sizes, int n_in,
                              void* d_out, int out_size) {
    const float* x   = (const float*)d_in[0];   // [512,64,512]
    const float* Wih = (const float*)d_in[1];   // [2048,512]
    const float* Whh = (const float*)d_in[2];   // [2048,512]
    const float* bih = (const float*)d_in[3];   // [2048]
    const float* bhh = (const float*)d_in[4];   // [2048]
    float* out = (float*)d_out;                 // [512,64,512]

    cudaFuncSetAttribute(lstm_rec, cudaFuncAttributeMaxDynamicSharedMemorySize, REC_SMEM);
    cudaFuncSetAttribute(gemm_tc, cudaFuncAttributeMaxDynamicSharedMemorySize, GEMM_SMEM);

    conv_a<<<8192, 256>>>(x);
    conv_w<<<1024, 256>>>(Wih);
    gemm_tc<<<dim3(16, 256), 256, GEMM_SMEM>>>(bih, bhh);
    lstm_rec<<<128, 512, REC_SMEM>>>(Whh, out);
}